// round 7
// baseline (speedup 1.0000x reference)
#include <cuda_runtime.h>
#include <cuda_bf16.h>
#include <cstdint>
#include <cstddef>

// ---------------------------------------------------------------------------
// Constants (total_steps=1000 -> K=10 bins of S=100)
// ---------------------------------------------------------------------------
#define T_STEPS 1000
#define SBIN    100
#define KBINS   10

#define H0 100
#define W0 368
#define H1 50
#define W1 184
#define H2 25
#define W2 92
#define H3 13
#define W3 46
#define H4 7
#define W4 23

#define P0 (H0*W0)   // 36800
#define P1 (H1*W1)   // 9200
#define P2 (H2*W2)   // 2300
#define P3 (H3*W3)   // 598
#define P4 (H4*W4)   // 161

#define N1 (4*P1)    // 36800
#define N2 (8*P2)    // 18400
#define N3 (16*P3)   // 9568
#define N4 (32*P4)   // 5152

// ---------------------------------------------------------------------------
// Scratch (device globals; allocation-free per harness rules).
// Referenced directly from device code -- no cudaGetSymbolAddress needed.
// ---------------------------------------------------------------------------
__device__ float         g_c1[(size_t)T_STEPS * N1];
__device__ unsigned char g_s1[(size_t)T_STEPS * N1];
__device__ float         g_c2[(size_t)T_STEPS * N2];
__device__ unsigned char g_s2[(size_t)T_STEPS * N2];
__device__ float         g_c3[(size_t)T_STEPS * N3];
__device__ unsigned char g_s3[(size_t)T_STEPS * N3];
__device__ float         g_c4[(size_t)T_STEPS * N4];

__device__ float g_skip1[80  * P1];
__device__ float g_skip2[160 * P2];
__device__ float g_skip3[320 * P3];
__device__ float g_skip4[640 * P4];

__device__ float g_d4[64 * P4];
__device__ float g_u4[64 * P3];
__device__ float g_d3[32 * P3];
__device__ float g_u3[32 * P2];
__device__ float g_d2[16 * P2];
__device__ float g_u2[16 * P1];
__device__ float g_d1[8  * P1];
__device__ float g_u1[8  * P0];

// Device-side buffer selectors (compile-time)
template<int L> __device__ __forceinline__ float* cbuf_of() {
    if constexpr (L == 1) return g_c1;
    else if constexpr (L == 2) return g_c2;
    else if constexpr (L == 3) return g_c3;
    else return g_c4;
}
template<int L> __device__ __forceinline__ unsigned char* sbuf_of() {
    if constexpr (L == 1) return g_s1;
    else if constexpr (L == 2) return g_s2;
    else return g_s3;
}
template<int L> __device__ __forceinline__ float* skip_of() {
    if constexpr (L == 1) return g_skip1;
    else if constexpr (L == 2) return g_skip2;
    else if constexpr (L == 3) return g_skip3;
    else return g_skip4;
}

// ---------------------------------------------------------------------------
// Layer-1 conv: x[t,1,100,368] -> g_c1[t,4,50,184]  (stride 2, SAME pad_lo=0)
// One thread = (t, output pos), all 4 out channels.
// ---------------------------------------------------------------------------
__global__ void conv1_kernel(const float* __restrict__ x,
                             const float* __restrict__ w1,
                             const float* __restrict__ b1) {
    __shared__ float ws[40];
    if (threadIdx.x < 36) ws[threadIdx.x] = w1[threadIdx.x];
    if (threadIdx.x < 4)  ws[36 + threadIdx.x] = b1[threadIdx.x];
    __syncthreads();

    int idx = blockIdx.x * blockDim.x + threadIdx.x;
    if (idx >= T_STEPS * P1) return;
    int t = idx / P1;
    int pos = idx - t * P1;
    int oh = pos / W1, ow = pos - oh * W1;

    const float* xt = x + (size_t)t * P0;
    float a0 = ws[36], a1 = ws[37], a2 = ws[38], a3 = ws[39];
    #pragma unroll
    for (int kh = 0; kh < 3; kh++) {
        int r = 2 * oh + kh;
        if (r >= H0) continue;
        #pragma unroll
        for (int kw = 0; kw < 3; kw++) {
            int cc = 2 * ow + kw;
            if (cc >= W0) continue;
            float v = __ldg(&xt[r * W0 + cc]);
            int tp = kh * 3 + kw;
            a0 = __fmaf_rn(v, ws[tp],      a0);
            a1 = __fmaf_rn(v, ws[9 + tp],  a1);
            a2 = __fmaf_rn(v, ws[18 + tp], a2);
            a3 = __fmaf_rn(v, ws[27 + tp], a3);
        }
    }
    float* out = g_c1 + (size_t)t * N1 + pos;
    out[0]      = a0;
    out[P1]     = a1;
    out[2 * P1] = a2;
    out[3 * P1] = a3;
}

// ---------------------------------------------------------------------------
// Spike conv (stride 2, SAME): spikes of layer L-1 -> currents of layer L.
// One thread = (t, pos), all COUT channels. Weights transposed in shared so
// a firing input adds a contiguous COUT-vector. PH = pad_lo on height
// (pad_lo on width is 0 for all layers here).
// ---------------------------------------------------------------------------
template<int L, int CIN, int COUT, int IH, int IW, int OH, int OW, int PH>
__global__ void convs_kernel(const float* __restrict__ w,
                             const float* __restrict__ b) {
    constexpr int P  = OH * OW;
    constexpr int NI = CIN * IH * IW;
    constexpr int NW = CIN * 9 * COUT;
    const unsigned char* __restrict__ spk = sbuf_of<L - 1>();
    float* __restrict__ cbuf = cbuf_of<L>();

    __shared__ __align__(16) float ws[NW];
    __shared__ float bs[COUT];
    for (int i = threadIdx.x; i < NW; i += blockDim.x) {
        int oc = i / (CIN * 9);
        int j  = i - oc * (CIN * 9);        // ic*9 + tap
        ws[j * COUT + oc] = w[i];
    }
    for (int i = threadIdx.x; i < COUT; i += blockDim.x) bs[i] = b[i];
    __syncthreads();

    int idx = blockIdx.x * blockDim.x + threadIdx.x;
    if (idx >= T_STEPS * P) return;
    int t = idx / P;
    int pos = idx - t * P;
    int oh = pos / OW, ow = pos - oh * OW;

    float acc[COUT];
    #pragma unroll
    for (int o = 0; o < COUT; o++) acc[o] = bs[o];

    const unsigned char* sp = spk + (size_t)t * NI;
    #pragma unroll
    for (int kh = 0; kh < 3; kh++) {
        int r = 2 * oh + kh - PH;
        if (r < 0 || r >= IH) continue;
        #pragma unroll
        for (int kw = 0; kw < 3; kw++) {
            int cc = 2 * ow + kw;
            if (cc >= IW) continue;
            int tap = kh * 3 + kw;
            #pragma unroll
            for (int ic = 0; ic < CIN; ic++) {
                if (sp[ic * (IH * IW) + r * IW + cc]) {
                    const float* wv = &ws[(ic * 9 + tap) * COUT];
                    #pragma unroll
                    for (int o = 0; o < COUT; o++)
                        acc[o] = __fadd_rn(acc[o], wv[o]);
                }
            }
        }
    }
    float* out = cbuf + (size_t)t * (COUT * P) + pos;
    #pragma unroll
    for (int o = 0; o < COUT; o++) out[o * P] = acc[o];
}

// ---------------------------------------------------------------------------
// Per-neuron membrane scan for layer L. One thread per neuron; 20-deep
// double-buffered register prefetch on the coalesced current stream.
//   m = 0.9*m + c;  spk = (m > 1);  m -= spk;  bin sums of m and m*m.
// Writes spike bytes (L<4) and skip features per bin.
// skip layout: channel k*(2*C)+c = mean, k*(2*C)+C+c = std (torch cat order).
// ---------------------------------------------------------------------------
template<int L, int C, int P, bool WRITE_S>
__global__ void scan_kernel() {
    constexpr int N = C * P;
    constexpr int UF = 20;
    constexpr int NG = SBIN / UF;   // 5 groups per bin
    const float* __restrict__ cbuf = cbuf_of<L>();
    float* __restrict__ skip = skip_of<L>();

    int n = blockIdx.x * blockDim.x + threadIdx.x;
    if (n >= N) return;
    int c = n / P, pos = n - c * P;

    const float* cp = cbuf + n;
    float buf[2][UF];
    #pragma unroll
    for (int j = 0; j < UF; j++) buf[0][j] = __ldg(cp + (size_t)j * N);

    float m = 0.0f;
    int gidx = 0;
    for (int k = 0; k < KBINS; k++) {
        float sum = 0.0f, sq = 0.0f;
        for (int g = 0; g < NG; g++, gidx++) {
            int pb = gidx & 1;
            int tbase = gidx * UF;
            if (gidx + 1 < KBINS * NG) {
                #pragma unroll
                for (int j = 0; j < UF; j++)
                    buf[1 - pb][j] = __ldg(cp + (size_t)(tbase + UF + j) * N);
            }
            #pragma unroll
            for (int j = 0; j < UF; j++) {
                // exact mul-then-add mirrors BETA*m + conv
                m = __fadd_rn(__fmul_rn(0.9f, m), buf[pb][j]);
                bool spk = (m > 1.0f);        // == (m - 1 > 0) exactly in fp32
                if (WRITE_S)
                    sbuf_of<L>()[(size_t)(tbase + j) * N + n] =
                        spk ? (unsigned char)1 : (unsigned char)0;
                if (spk) m = __fadd_rn(m, -1.0f);   // soft reset (exact, Sterbenz)
                sum = __fadd_rn(sum, m);
                sq  = __fmaf_rn(m, m, sq);
            }
        }
        float mu  = __fdiv_rn(sum, (float)SBIN);
        float var = __fsub_rn(__fdiv_rn(sq, (float)SBIN), __fmul_rn(mu, mu));
        float sd  = __fsqrt_rn(fmaxf(var, 1e-8f));
        skip[(size_t)(k * 2 * C + c) * P + pos]     = mu;
        skip[(size_t)(k * 2 * C + C + c) * P + pos] = sd;
    }
}

// ---------------------------------------------------------------------------
// Decoder conv: stride 1, SAME (pad 1), input = concat(in1[C1], in2[C2]).
// STAGE selects buffers at compile time. One thread = (oc=blockIdx.y, pos).
// ---------------------------------------------------------------------------
template<int STAGE, int C1, int C2, int COUT, int HH, int WW>
__global__ void dconv_kernel(const float* __restrict__ w,
                             const float* __restrict__ b) {
    constexpr int P = HH * WW;
    constexpr int CTOT = C1 + C2;
    const float* in1;
    const float* in2;
    float* outp;
    if constexpr (STAGE == 4) { in1 = g_skip4; in2 = nullptr; outp = g_d4; }
    else if constexpr (STAGE == 3) { in1 = g_u4; in2 = g_skip3; outp = g_d3; }
    else if constexpr (STAGE == 2) { in1 = g_u3; in2 = g_skip2; outp = g_d2; }
    else { in1 = g_u2; in2 = g_skip1; outp = g_d1; }

    int oc = blockIdx.y;
    int pos = blockIdx.x * blockDim.x + threadIdx.x;
    if (pos >= P) return;
    int oh = pos / WW, ow = pos - oh * WW;

    bool rv[3], cv[3];
    #pragma unroll
    for (int kh = 0; kh < 3; kh++) { int r = oh + kh - 1; rv[kh] = (r >= 0 && r < HH); }
    #pragma unroll
    for (int kw = 0; kw < 3; kw++) { int cc = ow + kw - 1; cv[kw] = (cc >= 0 && cc < WW); }

    const float* wrow = w + (size_t)oc * CTOT * 9;
    float acc[4] = {__ldg(&b[oc]), 0.0f, 0.0f, 0.0f};
    #pragma unroll 4
    for (int ci = 0; ci < CTOT; ci++) {
        const float* src = (C2 == 0 || ci < C1) ? (in1 + (size_t)ci * P)
                                                : (in2 + (size_t)(ci - C1) * P);
        const float* wv = wrow + ci * 9;
        float a = acc[ci & 3];
        #pragma unroll
        for (int kh = 0; kh < 3; kh++) {
            if (!rv[kh]) continue;
            int r = oh + kh - 1;
            #pragma unroll
            for (int kw = 0; kw < 3; kw++) {
                if (!cv[kw]) continue;
                int cc = ow + kw - 1;
                a = __fmaf_rn(__ldg(&src[r * WW + cc]), __ldg(&wv[kh * 3 + kw]), a);
            }
        }
        acc[ci & 3] = a;
    }
    float rres = __fadd_rn(__fadd_rn(acc[0], acc[1]), __fadd_rn(acc[2], acc[3]));
    rres = fmaxf(rres, 0.0f);   // all decoder convs are followed by relu
    outp[(size_t)oc * P + pos] = rres;
}

// ---------------------------------------------------------------------------
// Bilinear upsample (half-pixel centers, edge clamp) matching
// jax.image.resize 'bilinear' for upsampling. STAGE selects buffers.
// ---------------------------------------------------------------------------
template<int STAGE, int C, int IHH, int IWW, int OHH, int OWW>
__global__ void upsample_kernel() {
    constexpr int OP = OHH * OWW;
    constexpr int IP = IHH * IWW;
    const float* in;
    float* outp;
    if constexpr (STAGE == 4) { in = g_d4; outp = g_u4; }
    else if constexpr (STAGE == 3) { in = g_d3; outp = g_u3; }
    else if constexpr (STAGE == 2) { in = g_d2; outp = g_u2; }
    else { in = g_d1; outp = g_u1; }

    int idx = blockIdx.x * blockDim.x + threadIdx.x;
    if (idx >= C * OP) return;
    int cch = idx / OP;
    int rem = idx - cch * OP;
    int oh = rem / OWW, ow = rem - oh * OWW;

    float sy = (oh + 0.5f) * ((float)IHH / (float)OHH) - 0.5f;
    float sx = (ow + 0.5f) * ((float)IWW / (float)OWW) - 0.5f;
    float fy = floorf(sy), fx = floorf(sx);
    float wy = sy - fy, wx = sx - fx;
    int y0 = (int)fy, x0 = (int)fx;
    int y0c = max(y0, 0), y1c = min(y0 + 1, IHH - 1);
    int x0c = max(x0, 0), x1c = min(x0 + 1, IWW - 1);

    const float* src = in + (size_t)cch * IP;
    float v00 = __ldg(&src[y0c * IWW + x0c]);
    float v01 = __ldg(&src[y0c * IWW + x1c]);
    float v10 = __ldg(&src[y1c * IWW + x0c]);
    float v11 = __ldg(&src[y1c * IWW + x1c]);
    float top = __fadd_rn(__fmul_rn(1.0f - wx, v00), __fmul_rn(wx, v01));
    float bot = __fadd_rn(__fmul_rn(1.0f - wx, v10), __fmul_rn(wx, v11));
    outp[idx] = __fadd_rn(__fmul_rn(1.0f - wy, top), __fmul_rn(wy, bot));
}

// ---------------------------------------------------------------------------
// Final 1x1 conv: g_u1[8,100,368] -> out[1,100,368]
// ---------------------------------------------------------------------------
__global__ void outconv_kernel(const float* __restrict__ wo,
                               const float* __restrict__ bo,
                               float* __restrict__ out) {
    int pos = blockIdx.x * blockDim.x + threadIdx.x;
    if (pos >= P0) return;
    float acc = __ldg(&bo[0]);
    #pragma unroll
    for (int cch = 0; cch < 8; cch++)
        acc = __fmaf_rn(g_u1[cch * P0 + pos], __ldg(&wo[cch]), acc);
    out[pos] = acc;
}

// ---------------------------------------------------------------------------
// Host launcher: kernel launches ONLY (maximally capture-safe).
// ---------------------------------------------------------------------------
static inline int cdiv(int a, int b) { return (a + b - 1) / b; }

extern "C" void kernel_launch(void* const* d_in, const int* in_sizes, int n_in,
                              void* d_out, int out_size) {
    const float* x   = (const float*)d_in[0];
    const float* w1  = (const float*)d_in[1];
    const float* b1  = (const float*)d_in[2];
    const float* w2  = (const float*)d_in[3];
    const float* b2  = (const float*)d_in[4];
    const float* w3  = (const float*)d_in[5];
    const float* b3  = (const float*)d_in[6];
    const float* w4  = (const float*)d_in[7];
    const float* b4  = (const float*)d_in[8];
    const float* dw4 = (const float*)d_in[9];
    const float* db4 = (const float*)d_in[10];
    const float* dw3 = (const float*)d_in[11];
    const float* db3 = (const float*)d_in[12];
    const float* dw2 = (const float*)d_in[13];
    const float* db2 = (const float*)d_in[14];
    const float* dw1 = (const float*)d_in[15];
    const float* db1 = (const float*)d_in[16];
    const float* wo  = (const float*)d_in[17];
    const float* bo  = (const float*)d_in[18];
    float* out = (float*)d_out;

    // ---- Encoder: alternating batched conv / per-neuron scan ----
    conv1_kernel<<<cdiv(T_STEPS * P1, 256), 256>>>(x, w1, b1);
    scan_kernel<1, 4, P1, true><<<cdiv(N1, 128), 128>>>();

    convs_kernel<2, 4, 8, H1, W1, H2, W2, 0>
        <<<cdiv(T_STEPS * P2, 128), 128>>>(w2, b2);
    scan_kernel<2, 8, P2, true><<<cdiv(N2, 128), 128>>>();

    convs_kernel<3, 8, 16, H2, W2, H3, W3, 1>
        <<<cdiv(T_STEPS * P3, 128), 128>>>(w3, b3);
    scan_kernel<3, 16, P3, true><<<cdiv(N3, 128), 128>>>();

    convs_kernel<4, 16, 32, H3, W3, H4, W4, 1>
        <<<cdiv(T_STEPS * P4, 128), 128>>>(w4, b4);
    scan_kernel<4, 32, P4, false><<<cdiv(N4, 128), 128>>>();

    // ---- Decoder ----
    {   dim3 grid(1, 64);   // dec4: 640 -> 64 @ 7x23
        dconv_kernel<4, 640, 0, 64, H4, W4><<<grid, 192>>>(dw4, db4);
    }
    upsample_kernel<4, 64, H4, W4, H3, W3><<<cdiv(64 * P3, 256), 256>>>();
    {   dim3 grid(cdiv(P3, 128), 32);   // dec3: 64+320 -> 32 @ 13x46
        dconv_kernel<3, 64, 320, 32, H3, W3><<<grid, 128>>>(dw3, db3);
    }
    upsample_kernel<3, 32, H3, W3, H2, W2><<<cdiv(32 * P2, 256), 256>>>();
    {   dim3 grid(cdiv(P2, 128), 16);   // dec2: 32+160 -> 16 @ 25x92
        dconv_kernel<2, 32, 160, 16, H2, W2><<<grid, 128>>>(dw2, db2);
    }
    upsample_kernel<2, 16, H2, W2, H1, W1><<<cdiv(16 * P1, 256), 256>>>();
    {   dim3 grid(cdiv(P1, 128), 8);    // dec1: 16+80 -> 8 @ 50x184
        dconv_kernel<1, 16, 80, 8, H1, W1><<<grid, 128>>>(dw1, db1);
    }
    upsample_kernel<1, 8, H1, W1, H0, W0><<<cdiv(8 * P0, 256), 256>>>();
    outconv_kernel<<<cdiv(P0, 256), 256>>>(wo, bo, out);
}

// round 8
// speedup vs baseline: 1.1672x; 1.1672x over previous
#include <cuda_runtime.h>
#include <cuda_bf16.h>
#include <cstdint>
#include <cstddef>

// ---------------------------------------------------------------------------
// Constants (total_steps=1000 -> K=10 bins of S=100)
// ---------------------------------------------------------------------------
#define T_STEPS 1000
#define SBIN    100
#define KBINS   10

#define H0 100
#define W0 368
#define H1 50
#define W1 184
#define H2 25
#define W2 92
#define H3 13
#define W3 46
#define H4 7
#define W4 23

#define P0 (H0*W0)   // 36800
#define P1 (H1*W1)   // 9200
#define P2 (H2*W2)   // 2300
#define P3 (H3*W3)   // 598
#define P4 (H4*W4)   // 161

#define N1 (4*P1)    // 36800
#define N2 (8*P2)    // 18400
#define N3 (16*P3)   // 9568
#define N4 (32*P4)   // 5152

// ---------------------------------------------------------------------------
// Scratch (device globals; allocation-free per harness rules).
// ---------------------------------------------------------------------------
__device__ float         g_c1[(size_t)T_STEPS * N1];
__device__ unsigned char g_s1[(size_t)T_STEPS * N1];
__device__ float         g_c2[(size_t)T_STEPS * N2];
__device__ unsigned char g_s2[(size_t)T_STEPS * N2];
__device__ float         g_c3[(size_t)T_STEPS * N3];
__device__ unsigned char g_s3[(size_t)T_STEPS * N3];
__device__ float         g_c4[(size_t)T_STEPS * N4];

__device__ float g_skip1[80  * P1];
__device__ float g_skip2[160 * P2];
__device__ float g_skip3[320 * P3];
__device__ float g_skip4[640 * P4];

__device__ float g_d4[64 * P4];
__device__ float g_u4[64 * P3];
__device__ float g_d3[32 * P3];
__device__ float g_u3[32 * P2];
__device__ float g_d2[16 * P2];
__device__ float g_u2[16 * P1];
__device__ float g_d1[8  * P1];
__device__ float g_u1[8  * P0];

// Device-side buffer selectors (compile-time)
template<int L> __device__ __forceinline__ float* cbuf_of() {
    if constexpr (L == 1) return g_c1;
    else if constexpr (L == 2) return g_c2;
    else if constexpr (L == 3) return g_c3;
    else return g_c4;
}
template<int L> __device__ __forceinline__ unsigned char* sbuf_of() {
    if constexpr (L == 1) return g_s1;
    else if constexpr (L == 2) return g_s2;
    else return g_s3;
}
template<int L> __device__ __forceinline__ float* skip_of() {
    if constexpr (L == 1) return g_skip1;
    else if constexpr (L == 2) return g_skip2;
    else if constexpr (L == 3) return g_skip3;
    else return g_skip4;
}

// ---------------------------------------------------------------------------
// Layer-1 conv: x[t,1,100,368] -> g_c1[t,4,50,184]  (stride 2, SAME pad_lo=0)
// ---------------------------------------------------------------------------
__global__ void conv1_kernel(const float* __restrict__ x,
                             const float* __restrict__ w1,
                             const float* __restrict__ b1) {
    __shared__ float ws[40];
    if (threadIdx.x < 36) ws[threadIdx.x] = w1[threadIdx.x];
    if (threadIdx.x < 4)  ws[36 + threadIdx.x] = b1[threadIdx.x];
    __syncthreads();

    int idx = blockIdx.x * blockDim.x + threadIdx.x;
    if (idx >= T_STEPS * P1) return;
    int t = idx / P1;
    int pos = idx - t * P1;
    int oh = pos / W1, ow = pos - oh * W1;

    const float* xt = x + (size_t)t * P0;
    float a0 = ws[36], a1 = ws[37], a2 = ws[38], a3 = ws[39];
    #pragma unroll
    for (int kh = 0; kh < 3; kh++) {
        int r = 2 * oh + kh;
        if (r >= H0) continue;
        #pragma unroll
        for (int kw = 0; kw < 3; kw++) {
            int cc = 2 * ow + kw;
            if (cc >= W0) continue;
            float v = __ldg(&xt[r * W0 + cc]);
            int tp = kh * 3 + kw;
            a0 = __fmaf_rn(v, ws[tp],      a0);
            a1 = __fmaf_rn(v, ws[9 + tp],  a1);
            a2 = __fmaf_rn(v, ws[18 + tp], a2);
            a3 = __fmaf_rn(v, ws[27 + tp], a3);
        }
    }
    float* out = g_c1 + (size_t)t * N1 + pos;
    out[0]      = a0;
    out[P1]     = a1;
    out[2 * P1] = a2;
    out[3 * P1] = a3;
}

// ---------------------------------------------------------------------------
// Spike conv (stride 2, SAME): spikes of layer L-1 -> currents of layer L.
// ---------------------------------------------------------------------------
template<int L, int CIN, int COUT, int IH, int IW, int OH, int OW, int PH>
__global__ void convs_kernel(const float* __restrict__ w,
                             const float* __restrict__ b) {
    constexpr int P  = OH * OW;
    constexpr int NI = CIN * IH * IW;
    constexpr int NW = CIN * 9 * COUT;
    const unsigned char* __restrict__ spk = sbuf_of<L - 1>();
    float* __restrict__ cbuf = cbuf_of<L>();

    __shared__ __align__(16) float ws[NW];
    __shared__ float bs[COUT];
    for (int i = threadIdx.x; i < NW; i += blockDim.x) {
        int oc = i / (CIN * 9);
        int j  = i - oc * (CIN * 9);        // ic*9 + tap
        ws[j * COUT + oc] = w[i];
    }
    for (int i = threadIdx.x; i < COUT; i += blockDim.x) bs[i] = b[i];
    __syncthreads();

    int idx = blockIdx.x * blockDim.x + threadIdx.x;
    if (idx >= T_STEPS * P) return;
    int t = idx / P;
    int pos = idx - t * P;
    int oh = pos / OW, ow = pos - oh * OW;

    float acc[COUT];
    #pragma unroll
    for (int o = 0; o < COUT; o++) acc[o] = bs[o];

    const unsigned char* sp = spk + (size_t)t * NI;
    #pragma unroll
    for (int kh = 0; kh < 3; kh++) {
        int r = 2 * oh + kh - PH;
        if (r < 0 || r >= IH) continue;
        #pragma unroll
        for (int kw = 0; kw < 3; kw++) {
            int cc = 2 * ow + kw;
            if (cc >= IW) continue;
            int tap = kh * 3 + kw;
            #pragma unroll
            for (int ic = 0; ic < CIN; ic++) {
                if (sp[ic * (IH * IW) + r * IW + cc]) {
                    const float* wv = &ws[(ic * 9 + tap) * COUT];
                    #pragma unroll
                    for (int o = 0; o < COUT; o++)
                        acc[o] = __fadd_rn(acc[o], wv[o]);
                }
            }
        }
    }
    float* out = cbuf + (size_t)t * (COUT * P) + pos;
    #pragma unroll
    for (int o = 0; o < COUT; o++) out[o * P] = acc[o];
}

// ---------------------------------------------------------------------------
// Per-neuron membrane scan, spill-free version.
// UF=25 so each 100-step bin = exactly 4 groups: A,B,A,B with COMPILE-TIME
// buffer selection (the R7 version used a runtime-indexed buf[2][UF], which
// ptxas demoted to local memory -> 6x slowdown).
// scan_group: process `proc` (25 serial membrane steps) while prefetching the
// next 25 currents into `pre`.
// ---------------------------------------------------------------------------
template<int N, bool WRITE_S>
__device__ __forceinline__ void scan_group(const float* __restrict__ cp,
                                           unsigned char* __restrict__ sb,
                                           int tproc,
                                           float (&proc)[25], float (&pre)[25],
                                           float& m, float& sum, float& sq) {
    const int tpre = tproc + 25;
    const bool dopre = (tpre < T_STEPS);
    if (dopre) {
        #pragma unroll
        for (int j = 0; j < 25; j++)
            pre[j] = __ldg(cp + (size_t)(tpre + j) * N);
    }
    #pragma unroll
    for (int j = 0; j < 25; j++) {
        // exact mul-then-add mirrors BETA*m + conv
        m = __fadd_rn(__fmul_rn(0.9f, m), proc[j]);
        bool spk = (m > 1.0f);              // == (m - 1 > 0) exactly in fp32
        if (WRITE_S)
            sb[(size_t)(tproc + j) * N] = spk ? (unsigned char)1
                                              : (unsigned char)0;
        if (spk) m = __fadd_rn(m, -1.0f);   // soft reset (exact, Sterbenz)
        sum = __fadd_rn(sum, m);
        sq  = __fmaf_rn(m, m, sq);
    }
}

template<int L, int C, int P, bool WRITE_S>
__global__ void scan_kernel() {
    constexpr int N = C * P;
    const float* __restrict__ cbuf = cbuf_of<L>();
    float* __restrict__ skip = skip_of<L>();

    int n = blockIdx.x * blockDim.x + threadIdx.x;
    if (n >= N) return;
    int c = n / P, pos = n - c * P;

    const float* cp = cbuf + n;
    unsigned char* sb = WRITE_S ? (sbuf_of<L>() + n) : (unsigned char*)0;

    float A[25], B[25];
    #pragma unroll
    for (int j = 0; j < 25; j++) A[j] = __ldg(cp + (size_t)j * N);

    float m = 0.0f;
    int t = 0;
    for (int k = 0; k < KBINS; k++) {
        float sum = 0.0f, sq = 0.0f;
        scan_group<N, WRITE_S>(cp, sb, t, A, B, m, sum, sq); t += 25;
        scan_group<N, WRITE_S>(cp, sb, t, B, A, m, sum, sq); t += 25;
        scan_group<N, WRITE_S>(cp, sb, t, A, B, m, sum, sq); t += 25;
        scan_group<N, WRITE_S>(cp, sb, t, B, A, m, sum, sq); t += 25;

        float mu  = __fdiv_rn(sum, (float)SBIN);
        float var = __fsub_rn(__fdiv_rn(sq, (float)SBIN), __fmul_rn(mu, mu));
        float sd  = __fsqrt_rn(fmaxf(var, 1e-8f));
        skip[(size_t)(k * 2 * C + c) * P + pos]     = mu;
        skip[(size_t)(k * 2 * C + C + c) * P + pos] = sd;
    }
}

// ---------------------------------------------------------------------------
// Decoder conv: stride 1, SAME (pad 1), input = concat(in1[C1], in2[C2]).
// ---------------------------------------------------------------------------
template<int STAGE, int C1, int C2, int COUT, int HH, int WW>
__global__ void dconv_kernel(const float* __restrict__ w,
                             const float* __restrict__ b) {
    constexpr int P = HH * WW;
    constexpr int CTOT = C1 + C2;
    const float* in1;
    const float* in2;
    float* outp;
    if constexpr (STAGE == 4) { in1 = g_skip4; in2 = nullptr; outp = g_d4; }
    else if constexpr (STAGE == 3) { in1 = g_u4; in2 = g_skip3; outp = g_d3; }
    else if constexpr (STAGE == 2) { in1 = g_u3; in2 = g_skip2; outp = g_d2; }
    else { in1 = g_u2; in2 = g_skip1; outp = g_d1; }

    int oc = blockIdx.y;
    int pos = blockIdx.x * blockDim.x + threadIdx.x;
    if (pos >= P) return;
    int oh = pos / WW, ow = pos - oh * WW;

    bool rv[3], cv[3];
    #pragma unroll
    for (int kh = 0; kh < 3; kh++) { int r = oh + kh - 1; rv[kh] = (r >= 0 && r < HH); }
    #pragma unroll
    for (int kw = 0; kw < 3; kw++) { int cc = ow + kw - 1; cv[kw] = (cc >= 0 && cc < WW); }

    const float* wrow = w + (size_t)oc * CTOT * 9;
    float acc[4] = {__ldg(&b[oc]), 0.0f, 0.0f, 0.0f};
    #pragma unroll 4
    for (int ci = 0; ci < CTOT; ci++) {
        const float* src = (C2 == 0 || ci < C1) ? (in1 + (size_t)ci * P)
                                                : (in2 + (size_t)(ci - C1) * P);
        const float* wv = wrow + ci * 9;
        float a = acc[ci & 3];
        #pragma unroll
        for (int kh = 0; kh < 3; kh++) {
            if (!rv[kh]) continue;
            int r = oh + kh - 1;
            #pragma unroll
            for (int kw = 0; kw < 3; kw++) {
                if (!cv[kw]) continue;
                int cc = ow + kw - 1;
                a = __fmaf_rn(__ldg(&src[r * WW + cc]), __ldg(&wv[kh * 3 + kw]), a);
            }
        }
        acc[ci & 3] = a;
    }
    float rres = __fadd_rn(__fadd_rn(acc[0], acc[1]), __fadd_rn(acc[2], acc[3]));
    rres = fmaxf(rres, 0.0f);   // all decoder convs are followed by relu
    outp[(size_t)oc * P + pos] = rres;
}

// ---------------------------------------------------------------------------
// Bilinear upsample (half-pixel centers, edge clamp).
// ---------------------------------------------------------------------------
template<int STAGE, int C, int IHH, int IWW, int OHH, int OWW>
__global__ void upsample_kernel() {
    constexpr int OP = OHH * OWW;
    constexpr int IP = IHH * IWW;
    const float* in;
    float* outp;
    if constexpr (STAGE == 4) { in = g_d4; outp = g_u4; }
    else if constexpr (STAGE == 3) { in = g_d3; outp = g_u3; }
    else if constexpr (STAGE == 2) { in = g_d2; outp = g_u2; }
    else { in = g_d1; outp = g_u1; }

    int idx = blockIdx.x * blockDim.x + threadIdx.x;
    if (idx >= C * OP) return;
    int cch = idx / OP;
    int rem = idx - cch * OP;
    int oh = rem / OWW, ow = rem - oh * OWW;

    float sy = (oh + 0.5f) * ((float)IHH / (float)OHH) - 0.5f;
    float sx = (ow + 0.5f) * ((float)IWW / (float)OWW) - 0.5f;
    float fy = floorf(sy), fx = floorf(sx);
    float wy = sy - fy, wx = sx - fx;
    int y0 = (int)fy, x0 = (int)fx;
    int y0c = max(y0, 0), y1c = min(y0 + 1, IHH - 1);
    int x0c = max(x0, 0), x1c = min(x0 + 1, IWW - 1);

    const float* src = in + (size_t)cch * IP;
    float v00 = __ldg(&src[y0c * IWW + x0c]);
    float v01 = __ldg(&src[y0c * IWW + x1c]);
    float v10 = __ldg(&src[y1c * IWW + x0c]);
    float v11 = __ldg(&src[y1c * IWW + x1c]);
    float top = __fadd_rn(__fmul_rn(1.0f - wx, v00), __fmul_rn(wx, v01));
    float bot = __fadd_rn(__fmul_rn(1.0f - wx, v10), __fmul_rn(wx, v11));
    outp[idx] = __fadd_rn(__fmul_rn(1.0f - wy, top), __fmul_rn(wy, bot));
}

// ---------------------------------------------------------------------------
// Final 1x1 conv: g_u1[8,100,368] -> out[1,100,368]
// ---------------------------------------------------------------------------
__global__ void outconv_kernel(const float* __restrict__ wo,
                               const float* __restrict__ bo,
                               float* __restrict__ out) {
    int pos = blockIdx.x * blockDim.x + threadIdx.x;
    if (pos >= P0) return;
    float acc = __ldg(&bo[0]);
    #pragma unroll
    for (int cch = 0; cch < 8; cch++)
        acc = __fmaf_rn(g_u1[cch * P0 + pos], __ldg(&wo[cch]), acc);
    out[pos] = acc;
}

// ---------------------------------------------------------------------------
// Host launcher: kernel launches ONLY.
// ---------------------------------------------------------------------------
static inline int cdiv(int a, int b) { return (a + b - 1) / b; }

extern "C" void kernel_launch(void* const* d_in, const int* in_sizes, int n_in,
                              void* d_out, int out_size) {
    const float* x   = (const float*)d_in[0];
    const float* w1  = (const float*)d_in[1];
    const float* b1  = (const float*)d_in[2];
    const float* w2  = (const float*)d_in[3];
    const float* b2  = (const float*)d_in[4];
    const float* w3  = (const float*)d_in[5];
    const float* b3  = (const float*)d_in[6];
    const float* w4  = (const float*)d_in[7];
    const float* b4  = (const float*)d_in[8];
    const float* dw4 = (const float*)d_in[9];
    const float* db4 = (const float*)d_in[10];
    const float* dw3 = (const float*)d_in[11];
    const float* db3 = (const float*)d_in[12];
    const float* dw2 = (const float*)d_in[13];
    const float* db2 = (const float*)d_in[14];
    const float* dw1 = (const float*)d_in[15];
    const float* db1 = (const float*)d_in[16];
    const float* wo  = (const float*)d_in[17];
    const float* bo  = (const float*)d_in[18];
    float* out = (float*)d_out;

    // ---- Encoder: alternating batched conv / per-neuron scan ----
    conv1_kernel<<<cdiv(T_STEPS * P1, 256), 256>>>(x, w1, b1);
    scan_kernel<1, 4, P1, true><<<cdiv(N1, 128), 128>>>();

    convs_kernel<2, 4, 8, H1, W1, H2, W2, 0>
        <<<cdiv(T_STEPS * P2, 128), 128>>>(w2, b2);
    scan_kernel<2, 8, P2, true><<<cdiv(N2, 128), 128>>>();

    convs_kernel<3, 8, 16, H2, W2, H3, W3, 1>
        <<<cdiv(T_STEPS * P3, 128), 128>>>(w3, b3);
    scan_kernel<3, 16, P3, true><<<cdiv(N3, 128), 128>>>();

    convs_kernel<4, 16, 32, H3, W3, H4, W4, 1>
        <<<cdiv(T_STEPS * P4, 128), 128>>>(w4, b4);
    scan_kernel<4, 32, P4, false><<<cdiv(N4, 128), 128>>>();

    // ---- Decoder ----
    {   dim3 grid(1, 64);   // dec4: 640 -> 64 @ 7x23
        dconv_kernel<4, 640, 0, 64, H4, W4><<<grid, 192>>>(dw4, db4);
    }
    upsample_kernel<4, 64, H4, W4, H3, W3><<<cdiv(64 * P3, 256), 256>>>();
    {   dim3 grid(cdiv(P3, 128), 32);   // dec3: 64+320 -> 32 @ 13x46
        dconv_kernel<3, 64, 320, 32, H3, W3><<<grid, 128>>>(dw3, db3);
    }
    upsample_kernel<3, 32, H3, W3, H2, W2><<<cdiv(32 * P2, 256), 256>>>();
    {   dim3 grid(cdiv(P2, 128), 16);   // dec2: 32+160 -> 16 @ 25x92
        dconv_kernel<2, 32, 160, 16, H2, W2><<<grid, 128>>>(dw2, db2);
    }
    upsample_kernel<2, 16, H2, W2, H1, W1><<<cdiv(16 * P1, 256), 256>>>();
    {   dim3 grid(cdiv(P1, 128), 8);    // dec1: 16+80 -> 8 @ 50x184
        dconv_kernel<1, 16, 80, 8, H1, W1><<<grid, 128>>>(dw1, db1);
    }
    upsample_kernel<1, 8, H1, W1, H0, W0><<<cdiv(8 * P0, 256), 256>>>();
    outconv_kernel<<<cdiv(P0, 256), 256>>>(wo, bo, out);
}